// round 12
// baseline (speedup 1.0000x reference)
#include <cuda_runtime.h>
#include <cuda_fp16.h>
#include <cstdint>
#include <math.h>

constexpr int T = 512;
constexpr int N = 1024;
constexpr int D = 256;
constexpr int M_ROWS = T * N;    // 524288
constexpr int NTILES = M_ROWS / 128;  // 4096

// scratch: scores e[t,n]
__device__ float g_e[M_ROWS];

// ======================= helpers =======================
__device__ __forceinline__ uint32_t smem_u32(const void* p) {
    uint32_t a;
    asm("{ .reg .u64 t; cvta.to.shared.u64 t, %1; cvt.u32.u64 %0, t; }"
        : "=r"(a) : "l"(p));
    return a;
}
__device__ __forceinline__ uint32_t sw128(uint32_t b) { return b ^ ((b >> 3) & 0x70); }

__device__ __forceinline__ void mbar_init(uint32_t a, uint32_t cnt) {
    asm volatile("mbarrier.init.shared.b64 [%0], %1;" :: "r"(a), "r"(cnt) : "memory");
}
__device__ __forceinline__ void mbar_arrive(uint32_t a) {
    asm volatile("mbarrier.arrive.release.cta.shared::cta.b64 _, [%0];" :: "r"(a) : "memory");
}
__device__ __forceinline__ void mbar_wait(uint32_t a, uint32_t parity) {
    asm volatile(
        "{\n\t.reg .pred P;\n"
        "W_%=:\n\t"
        "mbarrier.try_wait.parity.acquire.cta.shared::cta.b64 P, [%0], %1, 0x989680;\n\t"
        "@P bra.uni DN_%=;\n\t"
        "bra.uni W_%=;\n"
        "DN_%=:\n\t}"
        :: "r"(a), "r"(parity) : "memory");
}
__device__ __forceinline__ void sts128(uint32_t addr, uint32_t x, uint32_t y,
                                       uint32_t z, uint32_t w) {
    asm volatile("st.shared.v4.b32 [%0], {%1,%2,%3,%4};"
                 :: "r"(addr), "r"(x), "r"(y), "r"(z), "r"(w) : "memory");
}
__device__ __forceinline__ void ldsm_x4(uint32_t& r0, uint32_t& r1, uint32_t& r2,
                                        uint32_t& r3, uint32_t addr) {
    asm volatile("ldmatrix.sync.aligned.m8n8.x4.shared.b16 {%0,%1,%2,%3}, [%4];"
                 : "=r"(r0), "=r"(r1), "=r"(r2), "=r"(r3) : "r"(addr));
}
__device__ __forceinline__ void mma_f16(float c[4], const uint32_t a[4],
                                        uint32_t b0, uint32_t b1) {
    asm volatile(
        "mma.sync.aligned.m16n8k16.row.col.f32.f16.f16.f32 "
        "{%0,%1,%2,%3}, {%4,%5,%6,%7}, {%8,%9}, {%0,%1,%2,%3};\n"
        : "+f"(c[0]), "+f"(c[1]), "+f"(c[2]), "+f"(c[3])
        : "r"(a[0]), "r"(a[1]), "r"(a[2]), "r"(a[3]), "r"(b0), "r"(b1));
}
__device__ __forceinline__ uint32_t pack_h2(float a, float b) {
    __half2 h = __floats2half2_rn(a, b);
    return *reinterpret_cast<uint32_t*>(&h);
}
__device__ __forceinline__ float tanh_fast(float x) {
    float y;
    asm("tanh.approx.f32 %0, %1;" : "=f"(y) : "f"(x));
    return y;
}
#define CBAR() asm volatile("bar.sync 15, 256;" ::: "memory")

// ======================= K1: persistent fp16 score GEMM =======================
// Grid = #SMs. fc_w (fp16, 128KB) resident in smem; CTA loops tiles bid, bid+G...
// Tile = 128 rows x 256 e, K=256 in 4 chunks of 64. 12 warps: 0-7 consumers
// (64x64 each), 8-11 producers (A chunks, 4-stage 16KB ring). Epilogue of tile i
// is fused into chunk 0 of tile i+1 (MUFU overlaps HMMA); single CBAR per tile.

constexpr int S = 4;
constexpr int A_CH_BYTES = 128 * 64 * 2;        // 16384
constexpr int B_CH_BYTES = 256 * 64 * 2;        // 32768
constexpr int BUF0 = 4096;
constexpr int B_OFF = BUF0;                      // 4 chunks: 131072 B
constexpr int A_OFF = B_OFF + 4 * B_CH_BYTES;    // 135168
constexpr int SMEM_BYTES = A_OFF + S * A_CH_BYTES;  // 200704
constexpr int NTHREADS = 384;

// smem bytes: full[s]@ s*8, empty[s]@ 32+s*8; floats: fc_b@[256,512),
// score_w@[512,768), esum0@[768,896), esum1@[896,1024).

__global__ __launch_bounds__(NTHREADS, 1)
void score_kernel(const float* __restrict__ H, const float* __restrict__ fc_w,
                  const float* __restrict__ fc_b, const float* __restrict__ score_w) {
    extern __shared__ char smem[];
    float* smf = reinterpret_cast<float*>(smem);
    const uint32_t sb = smem_u32(smem);

    const int tid  = threadIdx.x;
    const int wid  = tid >> 5;
    const int lane = tid & 31;
    const int G    = gridDim.x;

    // ---- prologue: params, barriers, resident B (fc_w -> fp16, SW128) ----
    if (tid < 256) {
        smf[256 + tid] = fc_b[tid];
        smf[512 + tid] = score_w[tid];
        smf[768 + tid] = 0.0f;   // both esum buffers
    }
    if (tid == 0) {
#pragma unroll
        for (int s = 0; s < S; ++s) {
            mbar_init(sb + s * 8, 128);        // full[s]: producer arrivals
            mbar_init(sb + 32 + s * 8, 256);   // empty[s]: consumer arrivals
        }
    }
    for (int idx = tid; idx < 8192; idx += NTHREADS) {  // 16B blocks of B
        int c  = idx >> 11;
        int rm = idx & 2047;
        int e  = rm >> 3;
        int kb = rm & 7;
        const float4* p = reinterpret_cast<const float4*>(
            fc_w + (size_t)e * D + c * 64 + kb * 8);
        float4 v0 = p[0], v1 = p[1];
        sts128(sb + B_OFF + c * B_CH_BYTES + sw128((uint32_t)(e * 128 + kb * 16)),
               pack_h2(v0.x, v0.y), pack_h2(v0.z, v0.w),
               pack_h2(v1.x, v1.y), pack_h2(v1.z, v1.w));
    }
    __syncthreads();

    if (wid >= 8) {
        // ---------------- producers: stage A chunks ----------------
        const int pt = tid - 256;  // 0..127
        int lc = 0, s = 0, w = 0;
        for (int tile = blockIdx.x; tile < NTILES; tile += G) {
            const size_t rowbase = (size_t)tile * 128;
#pragma unroll
            for (int c = 0; c < 4; ++c) {
                if (lc >= S) mbar_wait(sb + 32 + s * 8, (uint32_t)((w - 1) & 1));
                const uint32_t a_s = sb + A_OFF + s * A_CH_BYTES;
                const float* Ag = H + rowbase * D + c * 64;
#pragma unroll
                for (int i = 0; i < 8; ++i) {
                    int blk = i * 128 + pt;
                    int row = blk >> 3, kb = blk & 7;
                    const float4* p = reinterpret_cast<const float4*>(
                        Ag + (size_t)row * D + kb * 8);
                    float4 v0 = p[0], v1 = p[1];
                    sts128(a_s + sw128((uint32_t)(row * 128 + kb * 16)),
                           pack_h2(v0.x, v0.y), pack_h2(v0.z, v0.w),
                           pack_h2(v1.x, v1.y), pack_h2(v1.z, v1.w));
                }
                mbar_arrive(sb + s * 8);
                ++lc; if (++s == S) { s = 0; w ^= 1; }
            }
        }
    } else {
        // ---------------- consumers ----------------
        const int wr0 = (wid >> 2) * 64;
        const int we0 = (wid & 3) * 64;
        const int grp = lane >> 3;
        const int rin = lane & 7;
        const int g4  = lane >> 2;
        const int t4  = lane & 3;

        int s = 0, w = 0, tl = 0;
        int prev_tile = -1;
        float acc[4][8][4];
#pragma unroll
        for (int mt = 0; mt < 4; ++mt)
#pragma unroll
            for (int nt = 0; nt < 8; ++nt)
#pragma unroll
                for (int i = 0; i < 4; ++i) acc[mt][nt][i] = 0.0f;
        float sum0[4], sum1[4];

        for (int tile = blockIdx.x; tile < NTILES; tile += G, ++tl) {
            // ======== chunk 0: fused epilogue of prev tile + MMA ========
            mbar_wait(sb + s * 8, (uint32_t)(w & 1));
            {
                const uint32_t a_s = sb + A_OFF + s * A_CH_BYTES;
                const uint32_t b_s = sb + B_OFF;   // c = 0
                // b-frags for kk = 0, all ntp
                uint32_t bf[4][4];
#pragma unroll
                for (int ntp = 0; ntp < 4; ++ntp) {
                    int row = we0 + ntp * 16 + (grp >> 1) * 8 + rin;
                    int kb  = (grp & 1);           // kk=0
                    ldsm_x4(bf[ntp][0], bf[ntp][1], bf[ntp][2], bf[ntp][3],
                            b_s + sw128((uint32_t)(row * 128 + kb * 16)));
                }
#pragma unroll
                for (int mt = 0; mt < 4; ++mt) {
                    // epilogue for prev tile's acc[mt] (MUFU overlaps HMMA below)
                    if (prev_tile >= 0) {
                        float sa = 0.0f, sb2 = 0.0f;
#pragma unroll
                        for (int nt = 0; nt < 8; ++nt) {
                            int e0 = we0 + nt * 8 + t4 * 2;
                            int e1 = e0 + 1;
                            float b0 = smf[256 + e0], b1 = smf[256 + e1];
                            float s0 = smf[512 + e0], s1 = smf[512 + e1];
                            float th0 = tanh_fast(acc[mt][nt][0] + b0);
                            float th1 = tanh_fast(acc[mt][nt][1] + b1);
                            float th2 = tanh_fast(acc[mt][nt][2] + b0);
                            float th3 = tanh_fast(acc[mt][nt][3] + b1);
                            sa  = fmaf(th0, s0, fmaf(th1, s1, sa));
                            sb2 = fmaf(th2, s0, fmaf(th3, s1, sb2));
                        }
                        sum0[mt] = sa; sum1[mt] = sb2;
                    }
                    // zero + chunk-0 MMAs for this mt
#pragma unroll
                    for (int nt = 0; nt < 8; ++nt)
#pragma unroll
                        for (int i = 0; i < 4; ++i) acc[mt][nt][i] = 0.0f;
                    uint32_t af[4];
                    {
                        int row = wr0 + mt * 16 + (grp & 1) * 8 + rin;
                        int kb  = (grp >> 1);      // kk=0
                        ldsm_x4(af[0], af[1], af[2], af[3],
                                a_s + sw128((uint32_t)(row * 128 + kb * 16)));
                    }
#pragma unroll
                    for (int ntp = 0; ntp < 4; ++ntp) {
                        mma_f16(acc[mt][2 * ntp],     af, bf[ntp][0], bf[ntp][1]);
                        mma_f16(acc[mt][2 * ntp + 1], af, bf[ntp][2], bf[ntp][3]);
                    }
                }
                // kk = 1..3 of chunk 0
#pragma unroll
                for (int kk = 1; kk < 4; ++kk) {
                    uint32_t a[4][4];
#pragma unroll
                    for (int mt = 0; mt < 4; ++mt) {
                        int row = wr0 + mt * 16 + (grp & 1) * 8 + rin;
                        int kb  = kk * 2 + (grp >> 1);
                        ldsm_x4(a[mt][0], a[mt][1], a[mt][2], a[mt][3],
                                a_s + sw128((uint32_t)(row * 128 + kb * 16)));
                    }
#pragma unroll
                    for (int ntp = 0; ntp < 4; ++ntp) {
                        int row = we0 + ntp * 16 + (grp >> 1) * 8 + rin;
                        int kb  = kk * 2 + (grp & 1);
                        uint32_t b0, b1, b2, b3;
                        ldsm_x4(b0, b1, b2, b3,
                                b_s + sw128((uint32_t)(row * 128 + kb * 16)));
#pragma unroll
                        for (int mt = 0; mt < 4; ++mt) {
                            mma_f16(acc[mt][2 * ntp],     a[mt], b0, b1);
                            mma_f16(acc[mt][2 * ntp + 1], a[mt], b2, b3);
                        }
                    }
                }
            }
            mbar_arrive(sb + 32 + s * 8);
            if (++s == S) { s = 0; w ^= 1; }

            // deferred reduce + g_e write for prev tile (single CBAR)
            if (prev_tile >= 0) {
                float* es = smf + 768 + ((tl - 1) & 1) * 128;
#pragma unroll
                for (int mt = 0; mt < 4; ++mt) {
                    float a0 = sum0[mt], a1 = sum1[mt];
                    a0 += __shfl_xor_sync(0xffffffffu, a0, 1);
                    a0 += __shfl_xor_sync(0xffffffffu, a0, 2);
                    a1 += __shfl_xor_sync(0xffffffffu, a1, 1);
                    a1 += __shfl_xor_sync(0xffffffffu, a1, 2);
                    if (t4 == 0) {
                        atomicAdd(&es[wr0 + mt * 16 + g4],     a0);
                        atomicAdd(&es[wr0 + mt * 16 + g4 + 8], a1);
                    }
                }
                CBAR();
                if (tid < 128) {
                    g_e[(size_t)prev_tile * 128 + tid] = es[tid];
                    es[tid] = 0.0f;
                }
            }

            // ======== chunks 1..3 ========
#pragma unroll
            for (int c = 1; c < 4; ++c) {
                mbar_wait(sb + s * 8, (uint32_t)(w & 1));
                const uint32_t a_s = sb + A_OFF + s * A_CH_BYTES;
                const uint32_t b_s = sb + B_OFF + c * B_CH_BYTES;
#pragma unroll
                for (int kk = 0; kk < 4; ++kk) {
                    uint32_t a[4][4];
#pragma unroll
                    for (int mt = 0; mt < 4; ++mt) {
                        int row = wr0 + mt * 16 + (grp & 1) * 8 + rin;
                        int kb  = kk * 2 + (grp >> 1);
                        ldsm_x4(a[mt][0], a[mt][1], a[mt][2], a[mt][3],
                                a_s + sw128((uint32_t)(row * 128 + kb * 16)));
                    }
#pragma unroll
                    for (int ntp = 0; ntp < 4; ++ntp) {
                        int row = we0 + ntp * 16 + (grp >> 1) * 8 + rin;
                        int kb  = kk * 2 + (grp & 1);
                        uint32_t b0, b1, b2, b3;
                        ldsm_x4(b0, b1, b2, b3,
                                b_s + sw128((uint32_t)(row * 128 + kb * 16)));
#pragma unroll
                        for (int mt = 0; mt < 4; ++mt) {
                            mma_f16(acc[mt][2 * ntp],     a[mt], b0, b1);
                            mma_f16(acc[mt][2 * ntp + 1], a[mt], b2, b3);
                        }
                    }
                }
                mbar_arrive(sb + 32 + s * 8);
                if (++s == S) { s = 0; w ^= 1; }
            }
            prev_tile = tile;
        }

        // ======== final epilogue for last tile ========
        if (prev_tile >= 0) {
            float* es = smf + 768 + ((tl - 1) & 1) * 128;
#pragma unroll
            for (int mt = 0; mt < 4; ++mt) {
                float sa = 0.0f, sb2 = 0.0f;
#pragma unroll
                for (int nt = 0; nt < 8; ++nt) {
                    int e0 = we0 + nt * 8 + t4 * 2;
                    int e1 = e0 + 1;
                    float b0 = smf[256 + e0], b1 = smf[256 + e1];
                    float s0 = smf[512 + e0], s1 = smf[512 + e1];
                    float th0 = tanh_fast(acc[mt][nt][0] + b0);
                    float th1 = tanh_fast(acc[mt][nt][1] + b1);
                    float th2 = tanh_fast(acc[mt][nt][2] + b0);
                    float th3 = tanh_fast(acc[mt][nt][3] + b1);
                    sa  = fmaf(th0, s0, fmaf(th1, s1, sa));
                    sb2 = fmaf(th2, s0, fmaf(th3, s1, sb2));
                }
                sa  += __shfl_xor_sync(0xffffffffu, sa, 1);
                sa  += __shfl_xor_sync(0xffffffffu, sa, 2);
                sb2 += __shfl_xor_sync(0xffffffffu, sb2, 1);
                sb2 += __shfl_xor_sync(0xffffffffu, sb2, 2);
                if (t4 == 0) {
                    atomicAdd(&es[wr0 + mt * 16 + g4],     sa);
                    atomicAdd(&es[wr0 + mt * 16 + g4 + 8], sb2);
                }
            }
            CBAR();
            if (tid < 128)
                g_e[(size_t)prev_tile * 128 + tid] = es[tid];
        }
    }
}

// ======================= K2: causal softmax prefix scan =======================
// One block per channel n; 128 threads, float2/lane over D=256; p[t] in smem;
// 8-deep register prefetch; streaming ld/st. (79.8% DRAM — at the LTS-cap floor.)

constexpr int PF = 8;

__global__ __launch_bounds__(128)
void scan_kernel(const float* __restrict__ H, float* __restrict__ C) {
    const int n = blockIdx.x;
    const int tid = threadIdx.x;
    __shared__ float p_sh[T];
    __shared__ float red[4];

    float ev[4];
    float mx = -INFINITY;
#pragma unroll
    for (int j = 0; j < 4; ++j) {
        ev[j] = g_e[(size_t)(tid * 4 + j) * N + n];
        mx = fmaxf(mx, ev[j]);
    }
#pragma unroll
    for (int o = 16; o; o >>= 1) mx = fmaxf(mx, __shfl_xor_sync(0xffffffffu, mx, o));
    if ((tid & 31) == 0) red[tid >> 5] = mx;
    __syncthreads();
    const float Mn = fmaxf(fmaxf(red[0], red[1]), fmaxf(red[2], red[3]));
#pragma unroll
    for (int j = 0; j < 4; ++j) p_sh[tid * 4 + j] = __expf(ev[j] - Mn);
    __syncthreads();

    const size_t ND = (size_t)N * D;
    const float* Hp = H + (size_t)n * D + tid * 2;
    float*       Cp = C + (size_t)n * D + tid * 2;

    float2 buf[PF];
#pragma unroll
    for (int j = 0; j < PF; ++j)
        buf[j] = __ldcs(reinterpret_cast<const float2*>(Hp + (size_t)j * ND));

    float nx = 0.f, ny = 0.f, den = 0.f;
#pragma unroll 8
    for (int t = 0; t < T - PF; ++t) {
        float2 h = buf[t & (PF - 1)];
        buf[t & (PF - 1)] =
            __ldcs(reinterpret_cast<const float2*>(Hp + (size_t)(t + PF) * ND));
        float p = p_sh[t];
        den += p;
        nx = fmaf(p, h.x, nx);
        ny = fmaf(p, h.y, ny);
        float inv = __fdividef(1.0f, den);
        float2 o; o.x = nx * inv; o.y = ny * inv;
        __stcs(reinterpret_cast<float2*>(Cp + (size_t)t * ND), o);
    }
#pragma unroll
    for (int t = T - PF; t < T; ++t) {
        float2 h = buf[t & (PF - 1)];
        float p = p_sh[t];
        den += p;
        nx = fmaf(p, h.x, nx);
        ny = fmaf(p, h.y, ny);
        float inv = __fdividef(1.0f, den);
        float2 o; o.x = nx * inv; o.y = ny * inv;
        __stcs(reinterpret_cast<float2*>(Cp + (size_t)t * ND), o);
    }
}

// ======================= launch =======================
extern "C" void kernel_launch(void* const* d_in, const int* in_sizes, int n_in,
                              void* d_out, int out_size) {
    const float* H       = (const float*)d_in[0];
    const float* fc_w    = (const float*)d_in[1];
    const float* fc_b    = (const float*)d_in[2];
    const float* score_w = (const float*)d_in[3];
    float* C = (float*)d_out;

    int G = 148;
    cudaDeviceGetAttribute(&G, cudaDevAttrMultiProcessorCount, 0);

    cudaFuncSetAttribute(score_kernel, cudaFuncAttributeMaxDynamicSharedMemorySize, SMEM_BYTES);
    score_kernel<<<G, NTHREADS, SMEM_BYTES>>>(H, fc_w, fc_b, score_w);
    scan_kernel<<<N, 128>>>(H, C);
}

// round 14
// speedup vs baseline: 1.2251x; 1.2251x over previous
#include <cuda_runtime.h>
#include <cuda_fp16.h>
#include <cstdint>
#include <math.h>

constexpr int T = 512;
constexpr int N = 1024;
constexpr int D = 256;
constexpr int M_ROWS = T * N;    // 524288
constexpr int NTILES = M_ROWS / 128;  // 4096

// scratch: scores e[t,n]
__device__ float g_e[M_ROWS];

// ======================= helpers =======================
__device__ __forceinline__ uint32_t smem_u32(const void* p) {
    uint32_t a;
    asm("{ .reg .u64 t; cvta.to.shared.u64 t, %1; cvt.u32.u64 %0, t; }"
        : "=r"(a) : "l"(p));
    return a;
}
__device__ __forceinline__ uint32_t sw128(uint32_t b) { return b ^ ((b >> 3) & 0x70); }

__device__ __forceinline__ void mbar_init(uint32_t a, uint32_t cnt) {
    asm volatile("mbarrier.init.shared.b64 [%0], %1;" :: "r"(a), "r"(cnt) : "memory");
}
__device__ __forceinline__ void mbar_arrive(uint32_t a) {
    asm volatile("mbarrier.arrive.release.cta.shared::cta.b64 _, [%0];" :: "r"(a) : "memory");
}
__device__ __forceinline__ void mbar_wait(uint32_t a, uint32_t parity) {
    asm volatile(
        "{\n\t.reg .pred P;\n"
        "W_%=:\n\t"
        "mbarrier.try_wait.parity.acquire.cta.shared::cta.b64 P, [%0], %1, 0x989680;\n\t"
        "@P bra.uni DN_%=;\n\t"
        "bra.uni W_%=;\n"
        "DN_%=:\n\t}"
        :: "r"(a), "r"(parity) : "memory");
}
__device__ __forceinline__ void sts128(uint32_t addr, uint32_t x, uint32_t y,
                                       uint32_t z, uint32_t w) {
    asm volatile("st.shared.v4.b32 [%0], {%1,%2,%3,%4};"
                 :: "r"(addr), "r"(x), "r"(y), "r"(z), "r"(w) : "memory");
}
__device__ __forceinline__ void ldsm_x4(uint32_t& r0, uint32_t& r1, uint32_t& r2,
                                        uint32_t& r3, uint32_t addr) {
    asm volatile("ldmatrix.sync.aligned.m8n8.x4.shared.b16 {%0,%1,%2,%3}, [%4];"
                 : "=r"(r0), "=r"(r1), "=r"(r2), "=r"(r3) : "r"(addr));
}
__device__ __forceinline__ void mma_f16(float c[4], const uint32_t a[4],
                                        uint32_t b0, uint32_t b1) {
    asm volatile(
        "mma.sync.aligned.m16n8k16.row.col.f32.f16.f16.f32 "
        "{%0,%1,%2,%3}, {%4,%5,%6,%7}, {%8,%9}, {%0,%1,%2,%3};\n"
        : "+f"(c[0]), "+f"(c[1]), "+f"(c[2]), "+f"(c[3])
        : "r"(a[0]), "r"(a[1]), "r"(a[2]), "r"(a[3]), "r"(b0), "r"(b1));
}
__device__ __forceinline__ uint32_t pack_h2(float a, float b) {
    __half2 h = __floats2half2_rn(a, b);
    return *reinterpret_cast<uint32_t*>(&h);
}
__device__ __forceinline__ float tanh_fast(float x) {
    float y;
    asm("tanh.approx.f32 %0, %1;" : "=f"(y) : "f"(x));
    return y;
}
#define CBAR() asm volatile("bar.sync 15, 256;" ::: "memory")

// ======================= K1: persistent fp16 score GEMM (R11 winner, verbatim) ===
// Grid = #SMs. fc_w (fp16, 128KB) resident in smem; CTA loops tiles bid, bid+G...
// Tile = 128 rows x 256 e, K=256 in 4 chunks of 64. 12 warps: 0-7 consumers
// (64x64 each), 8-11 producers (A chunks, 3-stage 16KB ring).

constexpr int S = 3;
constexpr int A_CH_BYTES = 128 * 64 * 2;        // 16384
constexpr int B_CH_BYTES = 256 * 64 * 2;        // 32768
constexpr int BUF0 = 4096;
constexpr int B_OFF = BUF0;                      // 4 chunks: 131072 B
constexpr int A_OFF = B_OFF + 4 * B_CH_BYTES;    // 135168
constexpr int SMEM_BYTES = A_OFF + S * A_CH_BYTES;  // 184320
constexpr int NTHREADS = 384;

__global__ __launch_bounds__(NTHREADS, 1)
void score_kernel(const float* __restrict__ H, const float* __restrict__ fc_w,
                  const float* __restrict__ fc_b, const float* __restrict__ score_w) {
    extern __shared__ char smem[];
    float* smf = reinterpret_cast<float*>(smem);
    const uint32_t sb = smem_u32(smem);

    const int tid  = threadIdx.x;
    const int wid  = tid >> 5;
    const int lane = tid & 31;
    const int G    = gridDim.x;

    // ---- prologue: params, barriers, resident B (fc_w -> fp16, SW128) ----
    if (tid < 256) {
        smf[256 + tid] = fc_b[tid];
        smf[512 + tid] = score_w[tid];
        smf[768 + tid] = 0.0f;   // both esum buffers
    }
    if (tid == 0) {
#pragma unroll
        for (int s = 0; s < S; ++s) {
            mbar_init(sb + s * 8, 128);        // full[s]: producer arrivals
            mbar_init(sb + 24 + s * 8, 256);   // empty[s]: consumer arrivals
        }
    }
    for (int idx = tid; idx < 8192; idx += NTHREADS) {  // 16B blocks of B
        int c  = idx >> 11;
        int rm = idx & 2047;
        int e  = rm >> 3;
        int kb = rm & 7;
        const float4* p = reinterpret_cast<const float4*>(
            fc_w + (size_t)e * D + c * 64 + kb * 8);
        float4 v0 = p[0], v1 = p[1];
        sts128(sb + B_OFF + c * B_CH_BYTES + sw128((uint32_t)(e * 128 + kb * 16)),
               pack_h2(v0.x, v0.y), pack_h2(v0.z, v0.w),
               pack_h2(v1.x, v1.y), pack_h2(v1.z, v1.w));
    }
    __syncthreads();

    if (wid >= 8) {
        // ---------------- producers: stage A chunks ----------------
        const int pt = tid - 256;  // 0..127
        int lc = 0, s = 0, w = 0;
        for (int tile = blockIdx.x; tile < NTILES; tile += G) {
            const size_t rowbase = (size_t)tile * 128;
#pragma unroll
            for (int c = 0; c < 4; ++c) {
                if (lc >= S) mbar_wait(sb + 24 + s * 8, (uint32_t)((w - 1) & 1));
                const uint32_t a_s = sb + A_OFF + s * A_CH_BYTES;
                const float* Ag = H + rowbase * D + c * 64;
#pragma unroll
                for (int i = 0; i < 8; ++i) {
                    int blk = i * 128 + pt;
                    int row = blk >> 3, kb = blk & 7;
                    const float4* p = reinterpret_cast<const float4*>(
                        Ag + (size_t)row * D + kb * 8);
                    float4 v0 = p[0], v1 = p[1];
                    sts128(a_s + sw128((uint32_t)(row * 128 + kb * 16)),
                           pack_h2(v0.x, v0.y), pack_h2(v0.z, v0.w),
                           pack_h2(v1.x, v1.y), pack_h2(v1.z, v1.w));
                }
                mbar_arrive(sb + s * 8);
                ++lc; if (++s == S) { s = 0; w ^= 1; }
            }
        }
    } else {
        // ---------------- consumers ----------------
        const int wr0 = (wid >> 2) * 64;
        const int we0 = (wid & 3) * 64;
        const int grp = lane >> 3;
        const int rin = lane & 7;
        const int g4  = lane >> 2;
        const int t4  = lane & 3;

        int lc = 0, s = 0, w = 0, tl = 0;
        for (int tile = blockIdx.x; tile < NTILES; tile += G, ++tl) {
            float acc[4][8][4];
#pragma unroll
            for (int mt = 0; mt < 4; ++mt)
#pragma unroll
                for (int nt = 0; nt < 8; ++nt)
#pragma unroll
                    for (int i = 0; i < 4; ++i) acc[mt][nt][i] = 0.0f;

#pragma unroll
            for (int c = 0; c < 4; ++c) {
                mbar_wait(sb + s * 8, (uint32_t)(w & 1));
                const uint32_t a_s = sb + A_OFF + s * A_CH_BYTES;
                const uint32_t b_s = sb + B_OFF + c * B_CH_BYTES;
#pragma unroll
                for (int kk = 0; kk < 4; ++kk) {
                    uint32_t a[4][4];
#pragma unroll
                    for (int mt = 0; mt < 4; ++mt) {
                        int row = wr0 + mt * 16 + (grp & 1) * 8 + rin;
                        int kb  = kk * 2 + (grp >> 1);
                        ldsm_x4(a[mt][0], a[mt][1], a[mt][2], a[mt][3],
                                a_s + sw128((uint32_t)(row * 128 + kb * 16)));
                    }
#pragma unroll
                    for (int ntp = 0; ntp < 4; ++ntp) {
                        int row = we0 + ntp * 16 + (grp >> 1) * 8 + rin;
                        int kb  = kk * 2 + (grp & 1);
                        uint32_t b0, b1, b2, b3;
                        ldsm_x4(b0, b1, b2, b3,
                                b_s + sw128((uint32_t)(row * 128 + kb * 16)));
#pragma unroll
                        for (int mt = 0; mt < 4; ++mt) {
                            mma_f16(acc[mt][2 * ntp],     a[mt], b0, b1);
                            mma_f16(acc[mt][2 * ntp + 1], a[mt], b2, b3);
                        }
                    }
                }
                mbar_arrive(sb + 24 + s * 8);
                ++lc; if (++s == S) { s = 0; w ^= 1; }
            }

            // ---- epilogue: e_row = sum_e tanh(acc + fc_b[e]) * score_w[e] ----
            float* es = smf + 768 + (tl & 1) * 128;
            float sum0[4] = {0.f, 0.f, 0.f, 0.f};
            float sum1[4] = {0.f, 0.f, 0.f, 0.f};
#pragma unroll
            for (int nt = 0; nt < 8; ++nt) {
                int e0 = we0 + nt * 8 + t4 * 2;
                int e1 = e0 + 1;
                float b0 = smf[256 + e0], b1 = smf[256 + e1];
                float s0 = smf[512 + e0], s1 = smf[512 + e1];
#pragma unroll
                for (int mt = 0; mt < 4; ++mt) {
                    float th0 = tanh_fast(acc[mt][nt][0] + b0);
                    float th1 = tanh_fast(acc[mt][nt][1] + b1);
                    float th2 = tanh_fast(acc[mt][nt][2] + b0);
                    float th3 = tanh_fast(acc[mt][nt][3] + b1);
                    sum0[mt] = fmaf(th0, s0, fmaf(th1, s1, sum0[mt]));
                    sum1[mt] = fmaf(th2, s0, fmaf(th3, s1, sum1[mt]));
                }
            }
#pragma unroll
            for (int mt = 0; mt < 4; ++mt) {
                float a0 = sum0[mt], a1 = sum1[mt];
                a0 += __shfl_xor_sync(0xffffffffu, a0, 1);
                a0 += __shfl_xor_sync(0xffffffffu, a0, 2);
                a1 += __shfl_xor_sync(0xffffffffu, a1, 1);
                a1 += __shfl_xor_sync(0xffffffffu, a1, 2);
                if (t4 == 0) {
                    atomicAdd(&es[wr0 + mt * 16 + g4],     a0);
                    atomicAdd(&es[wr0 + mt * 16 + g4 + 8], a1);
                }
            }
            CBAR();
            if (tid < 128) {
                g_e[(size_t)tile * 128 + tid] = es[tid];
                es[tid] = 0.0f;
            }
            CBAR();
        }
    }
}

// ======================= K2: causal softmax prefix scan =======================
// Grid (N, 2): block = (channel n, D-half). 128 threads, ONE float per thread
// (coalesced 512B/warp). Doubles grid warps 4096 -> 8192 (occ 43% -> ~86%) to
// push DRAM past 80%. p[t] replicated per half (cheap).

constexpr int PF = 8;

__global__ __launch_bounds__(128)
void scan_kernel(const float* __restrict__ H, float* __restrict__ C) {
    const int n   = blockIdx.x;
    const int d0  = blockIdx.y * 128 + threadIdx.x;   // this thread's dim
    const int tid = threadIdx.x;
    __shared__ float p_sh[T];
    __shared__ float red[4];

    // phase A: global max of e[:,n], then p[t] = exp(e-M)
    float ev[4];
    float mx = -INFINITY;
#pragma unroll
    for (int j = 0; j < 4; ++j) {
        ev[j] = g_e[(size_t)(tid * 4 + j) * N + n];
        mx = fmaxf(mx, ev[j]);
    }
#pragma unroll
    for (int o = 16; o; o >>= 1) mx = fmaxf(mx, __shfl_xor_sync(0xffffffffu, mx, o));
    if ((tid & 31) == 0) red[tid >> 5] = mx;
    __syncthreads();
    const float Mn = fmaxf(fmaxf(red[0], red[1]), fmaxf(red[2], red[3]));
#pragma unroll
    for (int j = 0; j < 4; ++j) p_sh[tid * 4 + j] = __expf(ev[j] - Mn);
    __syncthreads();

    // phase B: scan over t (one scalar lane per thread)
    const size_t ND = (size_t)N * D;
    const float* Hp = H + (size_t)n * D + d0;
    float*       Cp = C + (size_t)n * D + d0;

    float buf[PF];
#pragma unroll
    for (int j = 0; j < PF; ++j) buf[j] = __ldcs(Hp + (size_t)j * ND);

    float num = 0.f, den = 0.f;
#pragma unroll 8
    for (int t = 0; t < T - PF; ++t) {
        float h = buf[t & (PF - 1)];
        buf[t & (PF - 1)] = __ldcs(Hp + (size_t)(t + PF) * ND);
        float p = p_sh[t];
        den += p;
        num = fmaf(p, h, num);
        __stcs(Cp + (size_t)t * ND, num * __fdividef(1.0f, den));
    }
#pragma unroll
    for (int t = T - PF; t < T; ++t) {
        float h = buf[t & (PF - 1)];
        float p = p_sh[t];
        den += p;
        num = fmaf(p, h, num);
        __stcs(Cp + (size_t)t * ND, num * __fdividef(1.0f, den));
    }
}

// ======================= launch =======================
extern "C" void kernel_launch(void* const* d_in, const int* in_sizes, int n_in,
                              void* d_out, int out_size) {
    const float* H       = (const float*)d_in[0];
    const float* fc_w    = (const float*)d_in[1];
    const float* fc_b    = (const float*)d_in[2];
    const float* score_w = (const float*)d_in[3];
    float* C = (float*)d_out;

    int G = 148;
    cudaDeviceGetAttribute(&G, cudaDevAttrMultiProcessorCount, 0);

    cudaFuncSetAttribute(score_kernel, cudaFuncAttributeMaxDynamicSharedMemorySize, SMEM_BYTES);
    score_kernel<<<G, NTHREADS, SMEM_BYTES>>>(H, fc_w, fc_b, score_w);
    scan_kernel<<<dim3(N, 2), 128>>>(H, C);
}